// round 1
// baseline (speedup 1.0000x reference)
#include <cuda_runtime.h>
#include <cstdint>

// Problem constants
#define BB 8
#define NN 4096
#define CC 512
#define HH 8
#define HD 64
#define SCALE 0.125f               // HD^-0.5 = 1/8
#define BHNHD (BB*HH*NN*HD)        // 16,777,216 elements per tensor

// Scratch: q,k,v in [3][B][H][N][HD] layout; global query/key vectors
__device__ float g_qkv[3ull * BHNHD];
__device__ float g_gq[BB * HH * HD];
__device__ float g_gk[BB * HH * HD];

// ---------------------------------------------------------------------------
// Kernel 1: QKV projection GEMM.
// qkv[m, d] = sum_c x[m, c] * w_qkv[d, c]   (NT gemm, both K-contiguous)
// M = B*N = 32768, K = 512, D = 1536.
// Output scattered into g_qkv[t][b][h][n][e] with d = t*512 + h*64 + e.
// 128x128x8 tile, 256 threads, 8x8 per thread.
// ---------------------------------------------------------------------------
__global__ void __launch_bounds__(256) qkv_gemm(const float* __restrict__ X,
                                                const float* __restrict__ W)
{
    __shared__ float Xs[8][128];
    __shared__ float Ws[8][128];

    const int tid = threadIdx.x;
    const int m0 = blockIdx.y * 128;
    const int d0 = blockIdx.x * 128;

    const int lrow = tid >> 1;          // 0..127
    const int lq   = (tid & 1) * 4;     // 0 or 4

    const float* Xp = X + (size_t)(m0 + lrow) * CC + lq;
    const float* Wp = W + (size_t)(d0 + lrow) * CC + lq;

    const int ty = tid >> 4;            // 0..15
    const int tx = tid & 15;            // 0..15

    float acc[8][8];
#pragma unroll
    for (int i = 0; i < 8; i++)
#pragma unroll
        for (int j = 0; j < 8; j++) acc[i][j] = 0.0f;

    for (int k0 = 0; k0 < CC; k0 += 8) {
        float4 xv = *(const float4*)(Xp + k0);
        float4 wv = *(const float4*)(Wp + k0);
        Xs[lq + 0][lrow] = xv.x; Xs[lq + 1][lrow] = xv.y;
        Xs[lq + 2][lrow] = xv.z; Xs[lq + 3][lrow] = xv.w;
        Ws[lq + 0][lrow] = wv.x; Ws[lq + 1][lrow] = wv.y;
        Ws[lq + 2][lrow] = wv.z; Ws[lq + 3][lrow] = wv.w;
        __syncthreads();
#pragma unroll
        for (int kk = 0; kk < 8; kk++) {
            float4 a0 = *(const float4*)&Xs[kk][ty * 8];
            float4 a1 = *(const float4*)&Xs[kk][ty * 8 + 4];
            float4 b0 = *(const float4*)&Ws[kk][tx * 8];
            float4 b1 = *(const float4*)&Ws[kk][tx * 8 + 4];
            float a[8] = {a0.x, a0.y, a0.z, a0.w, a1.x, a1.y, a1.z, a1.w};
            float b[8] = {b0.x, b0.y, b0.z, b0.w, b1.x, b1.y, b1.z, b1.w};
#pragma unroll
            for (int i = 0; i < 8; i++)
#pragma unroll
                for (int j = 0; j < 8; j++) acc[i][j] += a[i] * b[j];
        }
        __syncthreads();
    }

    // Scatter epilogue into [3][B][H][N][HD]
#pragma unroll
    for (int i = 0; i < 8; i++) {
        int m = m0 + ty * 8 + i;
        int b = m >> 12;            // /4096
        int n = m & 4095;
#pragma unroll
        for (int j = 0; j < 8; j++) {
            int d = d0 + tx * 8 + j;
            int t = d >> 9;         // /512
            int rem = d & 511;
            int h = rem >> 6;
            int e = rem & 63;
            g_qkv[(((size_t)t * BB + b) * HH + h) * ((size_t)NN * HD)
                  + (size_t)n * HD + e] = acc[i][j];
        }
    }
}

// ---------------------------------------------------------------------------
// Kernel 2: attention pooling (used twice).
// pass2 == 0: src = q, weight = w_q[h]            -> g_gq[b,h,:]
// pass2 == 1: src = k, weight = w_k[h]*g_gq[b,h]  -> g_gk[b,h,:]
// One CTA per (b,h); 256 threads (8 warps). Softmax over N=4096, then
// weighted sum of src rows.
// ---------------------------------------------------------------------------
__global__ void __launch_bounds__(256) pool_kernel(const float* __restrict__ wh,
                                                   int pass2)
{
    __shared__ float logits[NN];      // 16 KB
    __shared__ float ws[HD];
    __shared__ float red[8][HD];
    __shared__ float rscratch[8];

    const int bh = blockIdx.x;
    const int h  = bh & 7;
    const int tid  = threadIdx.x;
    const int lane = tid & 31;
    const int warp = tid >> 5;

    const float* src = g_qkv + (pass2 ? (size_t)BHNHD : 0)
                       + (size_t)bh * NN * HD;
    float* gout = pass2 ? g_gk : g_gq;

    if (tid < HD) {
        float w = wh[h * HD + tid] * SCALE;
        if (pass2) w *= g_gq[bh * HD + tid];
        ws[tid] = w;
    }
    __syncthreads();

    // pass 1: logits + running max (warp per row, coalesced)
    float lmax = -1e30f;
    for (int n = warp; n < NN; n += 8) {
        const float* row = src + (size_t)n * HD;
        float v = row[lane] * ws[lane] + row[lane + 32] * ws[lane + 32];
#pragma unroll
        for (int o = 16; o; o >>= 1) v += __shfl_xor_sync(0xffffffffu, v, o);
        if (lane == 0) logits[n] = v;
        lmax = fmaxf(lmax, v);
    }
    if (lane == 0) rscratch[warp] = lmax;
    __syncthreads();
    if (tid == 0) {
        float m = rscratch[0];
        for (int i = 1; i < 8; i++) m = fmaxf(m, rscratch[i]);
        rscratch[0] = m;
    }
    __syncthreads();
    const float gmax = rscratch[0];
    __syncthreads();

    // pass 2: exponentiate + sum
    float lsum = 0.0f;
    for (int n = tid; n < NN; n += 256) {
        float e = expf(logits[n] - gmax);
        logits[n] = e;
        lsum += e;
    }
#pragma unroll
    for (int o = 16; o; o >>= 1) lsum += __shfl_xor_sync(0xffffffffu, lsum, o);
    if (lane == 0) rscratch[warp] = lsum;
    __syncthreads();
    if (tid == 0) {
        float s = 0.0f;
        for (int i = 0; i < 8; i++) s += rscratch[i];
        rscratch[0] = s;
    }
    __syncthreads();
    const float inv = 1.0f / rscratch[0];

    // pass 3: weighted sum of rows -> global vector
    float a0 = 0.0f, a1 = 0.0f;
    for (int n = warp; n < NN; n += 8) {
        float p = logits[n];
        const float* row = src + (size_t)n * HD;
        a0 += p * row[lane];
        a1 += p * row[lane + 32];
    }
    red[warp][lane] = a0;
    red[warp][lane + 32] = a1;
    __syncthreads();
    if (tid < HD) {
        float s = 0.0f;
#pragma unroll
        for (int w = 0; w < 8; w++) s += red[w][tid];
        gout[bh * HD + tid] = s * inv;
    }
}

// ---------------------------------------------------------------------------
// Kernel 3: output GEMM with fused u = (global_k ⊙ v) construction and
// epilogue  out = acc + b_proj + q_flat.
// out[m, d] = sum_c u[m, c] * w_proj[d, c],  M=32768, K=512, D=512.
// u[m, c] = g_gk[b, c>>6, c&63] * v[b, c>>6, n, c&63]
// ---------------------------------------------------------------------------
__global__ void __launch_bounds__(256) out_gemm(const float* __restrict__ W,
                                                const float* __restrict__ bproj,
                                                float* __restrict__ out)
{
    __shared__ float Xs[8][128];
    __shared__ float Ws[8][128];

    const int tid = threadIdx.x;
    const int m0 = blockIdx.y * 128;
    const int d0 = blockIdx.x * 128;

    const int lrow = tid >> 1;
    const int lq   = (tid & 1) * 4;

    const int m = m0 + lrow;
    const int b = m >> 12;
    const int n = m & 4095;

    const float* vbase = g_qkv + 2ull * BHNHD;
    const float* Wp = W + (size_t)(d0 + lrow) * CC + lq;

    const int ty = tid >> 4;
    const int tx = tid & 15;

    float acc[8][8];
#pragma unroll
    for (int i = 0; i < 8; i++)
#pragma unroll
        for (int j = 0; j < 8; j++) acc[i][j] = 0.0f;

    for (int k0 = 0; k0 < CC; k0 += 8) {
        int c = k0 + lq;
        int h = c >> 6, e = c & 63;
        const float* vp = vbase + ((size_t)(b * HH + h) * NN + n) * HD + e;
        float4 vv = *(const float4*)vp;
        float4 gk = *(const float4*)&g_gk[(b * HH + h) * HD + e];
        float4 wv = *(const float4*)(Wp + k0);
        Xs[lq + 0][lrow] = vv.x * gk.x; Xs[lq + 1][lrow] = vv.y * gk.y;
        Xs[lq + 2][lrow] = vv.z * gk.z; Xs[lq + 3][lrow] = vv.w * gk.w;
        Ws[lq + 0][lrow] = wv.x; Ws[lq + 1][lrow] = wv.y;
        Ws[lq + 2][lrow] = wv.z; Ws[lq + 3][lrow] = wv.w;
        __syncthreads();
#pragma unroll
        for (int kk = 0; kk < 8; kk++) {
            float4 a0 = *(const float4*)&Xs[kk][ty * 8];
            float4 a1 = *(const float4*)&Xs[kk][ty * 8 + 4];
            float4 b0 = *(const float4*)&Ws[kk][tx * 8];
            float4 b1 = *(const float4*)&Ws[kk][tx * 8 + 4];
            float a[8] = {a0.x, a0.y, a0.z, a0.w, a1.x, a1.y, a1.z, a1.w};
            float bw[8] = {b0.x, b0.y, b0.z, b0.w, b1.x, b1.y, b1.z, b1.w};
#pragma unroll
            for (int i = 0; i < 8; i++)
#pragma unroll
                for (int j = 0; j < 8; j++) acc[i][j] += a[i] * bw[j];
        }
        __syncthreads();
    }

    // epilogue: + b_proj[d] + q_flat[m, d]
#pragma unroll
    for (int i = 0; i < 8; i++) {
        int mm = m0 + ty * 8 + i;
        int bi = mm >> 12;
        int ni = mm & 4095;
#pragma unroll
        for (int j = 0; j < 8; j++) {
            int d = d0 + tx * 8 + j;
            int h = d >> 6, e = d & 63;
            float qv = g_qkv[((size_t)(bi * HH + h) * NN + ni) * HD + e];
            out[(size_t)mm * CC + d] = acc[i][j] + bproj[d] + qv;
        }
    }
}

// ---------------------------------------------------------------------------
extern "C" void kernel_launch(void* const* d_in, const int* in_sizes, int n_in,
                              void* d_out, int out_size)
{
    const float* x      = (const float*)d_in[0];
    const float* w_qkv  = (const float*)d_in[1];
    const float* w_proj = (const float*)d_in[2];
    const float* b_proj = (const float*)d_in[3];
    const float* w_q    = (const float*)d_in[4];
    const float* w_k    = (const float*)d_in[5];
    float* out = (float*)d_out;

    // 1) QKV projection: 32768 x 1536 x 512
    qkv_gemm<<<dim3(1536 / 128, 32768 / 128), 256>>>(x, w_qkv);

    // 2) alpha pooling of q -> global_q
    pool_kernel<<<BB * HH, 256>>>(w_q, 0);

    // 3) beta pooling of k (weighted by global_q*w_k) -> global_k
    pool_kernel<<<BB * HH, 256>>>(w_k, 1);

    // 4) output GEMM with fused u = gk ⊙ v, epilogue + b_proj + q
    out_gemm<<<dim3(512 / 128, 32768 / 128), 256>>>(w_proj, b_proj, out);
}

// round 2
// speedup vs baseline: 1.9785x; 1.9785x over previous
#include <cuda_runtime.h>
#include <cstdint>

#define BB 8
#define NN 4096
#define CC 512
#define HH 8
#define HD 64
#define SCALE 0.125f
#define BHNHD (BB*HH*NN*HD)

#define PAD 20          // smem row stride (16 k + 4 pad) -> conflict-free frags

__device__ float g_qkv[3ull * BHNHD];
__device__ float g_gq[BB * HH * HD];
__device__ float g_gk[BB * HH * HD];

__device__ __forceinline__ uint32_t f2tf(float f) {
    uint32_t r; asm("cvt.rna.tf32.f32 %0, %1;" : "=r"(r) : "f"(f)); return r;
}

__device__ __forceinline__ void mma_tf32(float* c, const uint32_t* a, const uint32_t* b) {
    asm volatile(
        "mma.sync.aligned.m16n8k8.row.col.f32.tf32.tf32.f32 "
        "{%0,%1,%2,%3},{%4,%5,%6,%7},{%8,%9},{%0,%1,%2,%3};"
        : "+f"(c[0]), "+f"(c[1]), "+f"(c[2]), "+f"(c[3])
        : "r"(a[0]), "r"(a[1]), "r"(a[2]), "r"(a[3]), "r"(b[0]), "r"(b[1]));
}

__device__ __forceinline__ void cvt_sts(uint32_t* dst, float4 v0, float4 v1) {
    uint4 p0 = make_uint4(f2tf(v0.x), f2tf(v0.y), f2tf(v0.z), f2tf(v0.w));
    uint4 p1 = make_uint4(f2tf(v1.x), f2tf(v1.y), f2tf(v1.z), f2tf(v1.w));
    *(uint4*)(dst)     = p0;
    *(uint4*)(dst + 4) = p1;
}

// ---------------------------------------------------------------------------
// Kernel 1: QKV projection GEMM (tensor cores, tf32).
// qkv[m, d] = sum_c x[m,c] * w_qkv[d,c]; M=32768, K=512, D=1536.
// CTA tile 128x128, Kstep=16, double-buffered smem, 8 warps of 64x32.
// Epilogue scatters into g_qkv[t][b][h][n][e].
// ---------------------------------------------------------------------------
__global__ void __launch_bounds__(256) qkv_gemm_tc(const float* __restrict__ X,
                                                   const float* __restrict__ W)
{
    __shared__ uint32_t As[2][128 * PAD];
    __shared__ uint32_t Bs[2][128 * PAD];

    const int tid  = threadIdx.x;
    const int m0   = blockIdx.y * 128;
    const int d0   = blockIdx.x * 128;

    const int lrow = tid >> 1;          // 0..127
    const int kq   = (tid & 1) * 8;     // 0 or 8

    const float* Xp = X + (size_t)(m0 + lrow) * CC + kq;
    const float* Wp = W + (size_t)(d0 + lrow) * CC + kq;

    const int lane = tid & 31;
    const int warp = tid >> 5;
    const int wm = (warp & 1) * 64;
    const int wn = (warp >> 1) * 32;
    const int lr = lane >> 2;
    const int lc = lane & 3;

    float acc[4][4][4] = {};

    float4 ra0 = *(const float4*)(Xp);
    float4 ra1 = *(const float4*)(Xp + 4);
    float4 rb0 = *(const float4*)(Wp);
    float4 rb1 = *(const float4*)(Wp + 4);
    cvt_sts(&As[0][lrow * PAD + kq], ra0, ra1);
    cvt_sts(&Bs[0][lrow * PAD + kq], rb0, rb1);
    __syncthreads();

    for (int it = 0; it < 32; ++it) {
        const int cur = it & 1;
        if (it < 31) {
            const float* xp = Xp + (it + 1) * 16;
            const float* wp = Wp + (it + 1) * 16;
            ra0 = *(const float4*)(xp);
            ra1 = *(const float4*)(xp + 4);
            rb0 = *(const float4*)(wp);
            rb1 = *(const float4*)(wp + 4);
        }
#pragma unroll
        for (int kh = 0; kh < 2; ++kh) {
            const int ks = kh * 8;
            uint32_t af[4][4];
            uint32_t bf[4][2];
#pragma unroll
            for (int mi = 0; mi < 4; ++mi) {
                int m = wm + mi * 16 + lr;
                af[mi][0] = As[cur][m * PAD + ks + lc];
                af[mi][1] = As[cur][(m + 8) * PAD + ks + lc];
                af[mi][2] = As[cur][m * PAD + ks + 4 + lc];
                af[mi][3] = As[cur][(m + 8) * PAD + ks + 4 + lc];
            }
#pragma unroll
            for (int ni = 0; ni < 4; ++ni) {
                int d = wn + ni * 8 + lr;
                bf[ni][0] = Bs[cur][d * PAD + ks + lc];
                bf[ni][1] = Bs[cur][d * PAD + ks + 4 + lc];
            }
#pragma unroll
            for (int mi = 0; mi < 4; ++mi)
#pragma unroll
                for (int ni = 0; ni < 4; ++ni)
                    mma_tf32(acc[mi][ni], af[mi], bf[ni]);
        }
        if (it < 31) {
            const int nxt = (it + 1) & 1;
            cvt_sts(&As[nxt][lrow * PAD + kq], ra0, ra1);
            cvt_sts(&Bs[nxt][lrow * PAD + kq], rb0, rb1);
            __syncthreads();
        }
    }

    // Scatter epilogue into [3][B][H][N][HD]
#pragma unroll
    for (int mi = 0; mi < 4; ++mi) {
#pragma unroll
        for (int ni = 0; ni < 4; ++ni) {
            int d = d0 + wn + ni * 8 + 2 * lc;
            int t = d >> 9;
            int h = (d >> 6) & 7;
            int e = d & 63;
#pragma unroll
            for (int half = 0; half < 2; ++half) {
                int m = m0 + wm + mi * 16 + lr + half * 8;
                int b = m >> 12;
                int n = m & 4095;
                float* p = &g_qkv[(((size_t)t * BB + b) * HH + h) * ((size_t)NN * HD)
                                  + (size_t)n * HD + e];
                p[0] = acc[mi][ni][half * 2 + 0];
                p[1] = acc[mi][ni][half * 2 + 1];
            }
        }
    }
}

// ---------------------------------------------------------------------------
// Kernel 2: attention pooling (softmax-weighted sum). Same as round 1.
// ---------------------------------------------------------------------------
__global__ void __launch_bounds__(256) pool_kernel(const float* __restrict__ wh,
                                                   int pass2)
{
    __shared__ float logits[NN];
    __shared__ float ws[HD];
    __shared__ float red[8][HD];
    __shared__ float rscratch[8];

    const int bh = blockIdx.x;
    const int h  = bh & 7;
    const int tid  = threadIdx.x;
    const int lane = tid & 31;
    const int warp = tid >> 5;

    const float* src = g_qkv + (pass2 ? (size_t)BHNHD : 0)
                       + (size_t)bh * NN * HD;
    float* gout = pass2 ? g_gk : g_gq;

    if (tid < HD) {
        float w = wh[h * HD + tid] * SCALE;
        if (pass2) w *= g_gq[bh * HD + tid];
        ws[tid] = w;
    }
    __syncthreads();

    float lmax = -1e30f;
    for (int n = warp; n < NN; n += 8) {
        const float* row = src + (size_t)n * HD;
        float v = row[lane] * ws[lane] + row[lane + 32] * ws[lane + 32];
#pragma unroll
        for (int o = 16; o; o >>= 1) v += __shfl_xor_sync(0xffffffffu, v, o);
        if (lane == 0) logits[n] = v;
        lmax = fmaxf(lmax, v);
    }
    if (lane == 0) rscratch[warp] = lmax;
    __syncthreads();
    if (tid == 0) {
        float m = rscratch[0];
        for (int i = 1; i < 8; i++) m = fmaxf(m, rscratch[i]);
        rscratch[0] = m;
    }
    __syncthreads();
    const float gmax = rscratch[0];
    __syncthreads();

    float lsum = 0.0f;
    for (int n = tid; n < NN; n += 256) {
        float e = expf(logits[n] - gmax);
        logits[n] = e;
        lsum += e;
    }
#pragma unroll
    for (int o = 16; o; o >>= 1) lsum += __shfl_xor_sync(0xffffffffu, lsum, o);
    if (lane == 0) rscratch[warp] = lsum;
    __syncthreads();
    if (tid == 0) {
        float s = 0.0f;
        for (int i = 0; i < 8; i++) s += rscratch[i];
        rscratch[0] = s;
    }
    __syncthreads();
    const float inv = 1.0f / rscratch[0];

    float a0 = 0.0f, a1 = 0.0f;
    for (int n = warp; n < NN; n += 8) {
        float p = logits[n];
        const float* row = src + (size_t)n * HD;
        a0 += p * row[lane];
        a1 += p * row[lane + 32];
    }
    red[warp][lane] = a0;
    red[warp][lane + 32] = a1;
    __syncthreads();
    if (tid < HD) {
        float s = 0.0f;
#pragma unroll
        for (int w = 0; w < 8; w++) s += red[w][tid];
        gout[bh * HD + tid] = s * inv;
    }
}

// ---------------------------------------------------------------------------
// Kernel 3: output GEMM (tensor cores, tf32) with fused u = gk ⊙ v loader
// and epilogue out = acc + b_proj + q_flat.  M=32768, K=512, D=512.
// ---------------------------------------------------------------------------
__global__ void __launch_bounds__(256) out_gemm_tc(const float* __restrict__ W,
                                                   const float* __restrict__ bproj,
                                                   float* __restrict__ out)
{
    __shared__ uint32_t As[2][128 * PAD];
    __shared__ uint32_t Bs[2][128 * PAD];

    const int tid  = threadIdx.x;
    const int m0   = blockIdx.y * 128;
    const int d0   = blockIdx.x * 128;

    const int lrow = tid >> 1;
    const int kq   = (tid & 1) * 8;

    const int m  = m0 + lrow;
    const int bb = m >> 12;
    const int nn = m & 4095;

    const float* vbase = g_qkv + 2ull * BHNHD;
    const float* Wp = W + (size_t)(d0 + lrow) * CC + kq;

    const int lane = tid & 31;
    const int warp = tid >> 5;
    const int wm = (warp & 1) * 64;
    const int wn = (warp >> 1) * 32;
    const int lr = lane >> 2;
    const int lc = lane & 3;

    float acc[4][4][4] = {};

    float4 ra0, ra1, rb0, rb1;

    // fused A loader: u[m, c] = g_gk[b, c>>6, c&63] * v[b, c>>6, n, c&63]
    auto loadA = [&](int k0, float4& r0, float4& r1) {
        int c = k0 + kq;
        int h = c >> 6, e = c & 63;
        const float* vp = vbase + ((size_t)(bb * HH + h) * NN + nn) * HD + e;
        const float* gp = &g_gk[(bb * HH + h) * HD + e];
        float4 v0 = *(const float4*)vp;
        float4 v1 = *(const float4*)(vp + 4);
        float4 g0 = *(const float4*)gp;
        float4 g1 = *(const float4*)(gp + 4);
        r0.x = v0.x * g0.x; r0.y = v0.y * g0.y; r0.z = v0.z * g0.z; r0.w = v0.w * g0.w;
        r1.x = v1.x * g1.x; r1.y = v1.y * g1.y; r1.z = v1.z * g1.z; r1.w = v1.w * g1.w;
    };

    loadA(0, ra0, ra1);
    rb0 = *(const float4*)(Wp);
    rb1 = *(const float4*)(Wp + 4);
    cvt_sts(&As[0][lrow * PAD + kq], ra0, ra1);
    cvt_sts(&Bs[0][lrow * PAD + kq], rb0, rb1);
    __syncthreads();

    for (int it = 0; it < 32; ++it) {
        const int cur = it & 1;
        if (it < 31) {
            loadA((it + 1) * 16, ra0, ra1);
            const float* wp = Wp + (it + 1) * 16;
            rb0 = *(const float4*)(wp);
            rb1 = *(const float4*)(wp + 4);
        }
#pragma unroll
        for (int kh = 0; kh < 2; ++kh) {
            const int ks = kh * 8;
            uint32_t af[4][4];
            uint32_t bf[4][2];
#pragma unroll
            for (int mi = 0; mi < 4; ++mi) {
                int mm = wm + mi * 16 + lr;
                af[mi][0] = As[cur][mm * PAD + ks + lc];
                af[mi][1] = As[cur][(mm + 8) * PAD + ks + lc];
                af[mi][2] = As[cur][mm * PAD + ks + 4 + lc];
                af[mi][3] = As[cur][(mm + 8) * PAD + ks + 4 + lc];
            }
#pragma unroll
            for (int ni = 0; ni < 4; ++ni) {
                int d = wn + ni * 8 + lr;
                bf[ni][0] = Bs[cur][d * PAD + ks + lc];
                bf[ni][1] = Bs[cur][d * PAD + ks + 4 + lc];
            }
#pragma unroll
            for (int mi = 0; mi < 4; ++mi)
#pragma unroll
                for (int ni = 0; ni < 4; ++ni)
                    mma_tf32(acc[mi][ni], af[mi], bf[ni]);
        }
        if (it < 31) {
            const int nxt = (it + 1) & 1;
            cvt_sts(&As[nxt][lrow * PAD + kq], ra0, ra1);
            cvt_sts(&Bs[nxt][lrow * PAD + kq], rb0, rb1);
            __syncthreads();
        }
    }

    // epilogue: + b_proj[d] + q_flat[m, d]
#pragma unroll
    for (int mi = 0; mi < 4; ++mi) {
#pragma unroll
        for (int ni = 0; ni < 4; ++ni) {
            int d = d0 + wn + ni * 8 + 2 * lc;
            int h = d >> 6, e = d & 63;
            float bp0 = bproj[d], bp1 = bproj[d + 1];
#pragma unroll
            for (int half = 0; half < 2; ++half) {
                int mm = m0 + wm + mi * 16 + lr + half * 8;
                int bi = mm >> 12;
                int ni2 = mm & 4095;
                const float* qp = &g_qkv[((size_t)(bi * HH + h) * NN + ni2) * HD + e];
                float* op = &out[(size_t)mm * CC + d];
                op[0] = acc[mi][ni][half * 2 + 0] + bp0 + qp[0];
                op[1] = acc[mi][ni][half * 2 + 1] + bp1 + qp[1];
            }
        }
    }
}

// ---------------------------------------------------------------------------
extern "C" void kernel_launch(void* const* d_in, const int* in_sizes, int n_in,
                              void* d_out, int out_size)
{
    const float* x      = (const float*)d_in[0];
    const float* w_qkv  = (const float*)d_in[1];
    const float* w_proj = (const float*)d_in[2];
    const float* b_proj = (const float*)d_in[3];
    const float* w_q    = (const float*)d_in[4];
    const float* w_k    = (const float*)d_in[5];
    float* out = (float*)d_out;

    qkv_gemm_tc<<<dim3(1536 / 128, 32768 / 128), 256>>>(x, w_qkv);
    pool_kernel<<<BB * HH, 256>>>(w_q, 0);
    pool_kernel<<<BB * HH, 256>>>(w_k, 1);
    out_gemm_tc<<<dim3(512 / 128, 32768 / 128), 256>>>(w_proj, b_proj, out);
}

// round 4
// speedup vs baseline: 2.0073x; 1.0146x over previous
#include <cuda_runtime.h>
#include <cstdint>

#define BB 8
#define NN 4096
#define CC 512
#define HH 8
#define HD 64
#define SCALE 0.125f
#define BHNHD (BB*HH*NN*HD)

#define PAD 20                  // words per smem row (16 k + 4 pad), conflict-free

__device__ float g_qkv[3ull * BHNHD];
__device__ float g_gq[BB * HH * HD];
__device__ float g_gk[BB * HH * HD];

__device__ __forceinline__ uint32_t f2tf(float f) {
    uint32_t r; asm("cvt.rna.tf32.f32 %0, %1;" : "=r"(r) : "f"(f)); return r;
}
__device__ __forceinline__ uint4 cvt4(float4 v) {
    return make_uint4(f2tf(v.x), f2tf(v.y), f2tf(v.z), f2tf(v.w));
}
__device__ __forceinline__ void mma_tf32(float* c, const uint32_t* a, const uint32_t* b) {
    asm volatile(
        "mma.sync.aligned.m16n8k8.row.col.f32.tf32.tf32.f32 "
        "{%0,%1,%2,%3},{%4,%5,%6,%7},{%8,%9},{%0,%1,%2,%3};"
        : "+f"(c[0]), "+f"(c[1]), "+f"(c[2]), "+f"(c[3])
        : "r"(a[0]), "r"(a[1]), "r"(a[2]), "r"(a[3]), "r"(b[0]), "r"(b[1]));
}

// Dynamic smem word offsets (CTA tile 256x128, k-chunk 16, double buffered)
//   A[buf] : 256 rows * PAD words   (5120 words / 20 KB each)
//   B[buf] : 128 rows * PAD words   (2560 words / 10 KB each)
//   gk     : 512 words (out_gemm only)
#define AW(buf)   ((buf) * 5120)
#define BW(buf)   (10240 + (buf) * 2560)
#define GKW       15360
#define SMEM_QKV  (15360 * 4)
#define SMEM_OUT  ((15360 + 512) * 4)

// ---------------------------------------------------------------------------
// Kernel 1: QKV GEMM (tf32 mma.sync). qkv[m,d] = sum_c x[m,c]*w[d,c]
// M=32768, D=1536, K=512. CTA 256x128, warp 64x64 (4m x 2n warps).
// ---------------------------------------------------------------------------
__global__ void __launch_bounds__(256) qkv_gemm_v2(const float* __restrict__ X,
                                                   const float* __restrict__ W)
{
    extern __shared__ uint32_t sm[];

    const int tid = threadIdx.x;
    const int m0 = blockIdx.y * 256;
    const int d0 = blockIdx.x * 128;

    // loaders: A = 4 float4/thread/stage, B = 2 float4/thread/stage
    int arow[4], ac4[4], brow[2], bc4[2];
    const float* Ap[4]; const float* Bp[2];
#pragma unroll
    for (int i = 0; i < 4; i++) {
        int id = i * 256 + tid;
        arow[i] = id >> 2; ac4[i] = id & 3;
        Ap[i] = X + (size_t)(m0 + arow[i]) * CC + ac4[i] * 4;
    }
#pragma unroll
    for (int i = 0; i < 2; i++) {
        int id = i * 256 + tid;
        brow[i] = id >> 2; bc4[i] = id & 3;
        Bp[i] = W + (size_t)(d0 + brow[i]) * CC + bc4[i] * 4;
    }

    const int lane = tid & 31;
    const int warp = tid >> 5;
    const int wm = (warp & 3) * 64;
    const int wn = (warp >> 2) * 64;
    const int lr = lane >> 2;
    const int lc = lane & 3;

    float acc[4][8][4] = {};

    // stage 0
#pragma unroll
    for (int i = 0; i < 4; i++)
        *(uint4*)&sm[AW(0) + arow[i] * PAD + ac4[i] * 4] = cvt4(*(const float4*)Ap[i]);
#pragma unroll
    for (int i = 0; i < 2; i++)
        *(uint4*)&sm[BW(0) + brow[i] * PAD + bc4[i] * 4] = cvt4(*(const float4*)Bp[i]);
    __syncthreads();

    float4 pa[4], pb[2];
    for (int s = 0; s < 32; ++s) {
        const int cur = s & 1;
        if (s < 31) {
#pragma unroll
            for (int i = 0; i < 4; i++) pa[i] = *(const float4*)(Ap[i] + (s + 1) * 16);
#pragma unroll
            for (int i = 0; i < 2; i++) pb[i] = *(const float4*)(Bp[i] + (s + 1) * 16);
        }
#pragma unroll
        for (int kh = 0; kh < 2; ++kh) {
            const int ks = kh * 8;
            uint32_t af[4][4], bf[8][2];
#pragma unroll
            for (int mi = 0; mi < 4; ++mi) {
                int r = wm + mi * 16 + lr;
                af[mi][0] = sm[AW(cur) + r * PAD + ks + lc];
                af[mi][1] = sm[AW(cur) + (r + 8) * PAD + ks + lc];
                af[mi][2] = sm[AW(cur) + r * PAD + ks + 4 + lc];
                af[mi][3] = sm[AW(cur) + (r + 8) * PAD + ks + 4 + lc];
            }
#pragma unroll
            for (int ni = 0; ni < 8; ++ni) {
                int r = wn + ni * 8 + lr;
                bf[ni][0] = sm[BW(cur) + r * PAD + ks + lc];
                bf[ni][1] = sm[BW(cur) + r * PAD + ks + 4 + lc];
            }
#pragma unroll
            for (int mi = 0; mi < 4; ++mi)
#pragma unroll
                for (int ni = 0; ni < 8; ++ni)
                    mma_tf32(acc[mi][ni], af[mi], bf[ni]);
        }
        if (s < 31) {
            const int nxt = (s + 1) & 1;
#pragma unroll
            for (int i = 0; i < 4; i++)
                *(uint4*)&sm[AW(nxt) + arow[i] * PAD + ac4[i] * 4] = cvt4(pa[i]);
#pragma unroll
            for (int i = 0; i < 2; i++)
                *(uint4*)&sm[BW(nxt) + brow[i] * PAD + bc4[i] * 4] = cvt4(pb[i]);
            __syncthreads();
        }
    }

    // scatter epilogue into g_qkv[t][b][h][n][e]
#pragma unroll
    for (int mi = 0; mi < 4; ++mi) {
#pragma unroll
        for (int ni = 0; ni < 8; ++ni) {
            int d = d0 + wn + ni * 8 + 2 * lc;
            int t = d >> 9, h = (d >> 6) & 7, e = d & 63;
#pragma unroll
            for (int half = 0; half < 2; ++half) {
                int m = m0 + wm + mi * 16 + lr + half * 8;
                int b = m >> 12, n = m & 4095;
                float* p = &g_qkv[(((size_t)t * BB + b) * HH + h) * ((size_t)NN * HD)
                                  + (size_t)n * HD + e];
                p[0] = acc[mi][ni][half * 2 + 0];
                p[1] = acc[mi][ni][half * 2 + 1];
            }
        }
    }
}

// ---------------------------------------------------------------------------
// Kernel 3: output GEMM (tf32 mma.sync), fused u = gk (x) v loader and
// epilogue out = acc + b_proj + q.  M=32768, D=512, K=512. CTA 256x128.
// ---------------------------------------------------------------------------
__global__ void __launch_bounds__(256) out_gemm_v2(const float* __restrict__ W,
                                                   const float* __restrict__ bproj,
                                                   float* __restrict__ out)
{
    extern __shared__ uint32_t sm[];
    float* gks = (float*)&sm[GKW];

    const int tid = threadIdx.x;
    const int m0 = blockIdx.y * 256;
    const int d0 = blockIdx.x * 128;
    const int bb = m0 >> 12;             // batch (tile never straddles batches)
    const int n0 = m0 & 4095;

    if (tid < 128)
        *(float4*)&gks[tid * 4] = *(const float4*)&g_gk[bb * CC + tid * 4];

    int arow[4], ac4[4], brow[2], bc4[2];
    const float* Bp[2];
#pragma unroll
    for (int i = 0; i < 4; i++) {
        int id = i * 256 + tid;
        arow[i] = id >> 2; ac4[i] = id & 3;
    }
#pragma unroll
    for (int i = 0; i < 2; i++) {
        int id = i * 256 + tid;
        brow[i] = id >> 2; bc4[i] = id & 3;
        Bp[i] = W + (size_t)(d0 + brow[i]) * CC + bc4[i] * 4;
    }

    const float* vbase = g_qkv + 2ull * BHNHD;
    const int lane = tid & 31;
    const int warp = tid >> 5;
    const int wm = (warp & 3) * 64;
    const int wn = (warp >> 2) * 64;
    const int lr = lane >> 2;
    const int lc = lane & 3;

    float acc[4][8][4] = {};

    __syncthreads();   // gks visible

    // fused A loader: u[m, c] = gk[c] * v[b, c>>6, n, c&63], c = s*16 + c4*4
    auto loadA = [&](int s, int i) -> float4 {
        int c = s * 16 + ac4[i] * 4;
        int h = c >> 6, e = c & 63;
        float4 v = *(const float4*)(vbase
            + ((size_t)(bb * HH + h) * NN + n0 + arow[i]) * HD + e);
        float4 g = *(const float4*)&gks[c];
        return make_float4(v.x * g.x, v.y * g.y, v.z * g.z, v.w * g.w);
    };

#pragma unroll
    for (int i = 0; i < 4; i++)
        *(uint4*)&sm[AW(0) + arow[i] * PAD + ac4[i] * 4] = cvt4(loadA(0, i));
#pragma unroll
    for (int i = 0; i < 2; i++)
        *(uint4*)&sm[BW(0) + brow[i] * PAD + bc4[i] * 4] = cvt4(*(const float4*)Bp[i]);
    __syncthreads();

    float4 pa[4], pb[2];
    for (int s = 0; s < 32; ++s) {
        const int cur = s & 1;
        if (s < 31) {
#pragma unroll
            for (int i = 0; i < 4; i++) pa[i] = loadA(s + 1, i);
#pragma unroll
            for (int i = 0; i < 2; i++) pb[i] = *(const float4*)(Bp[i] + (s + 1) * 16);
        }
#pragma unroll
        for (int kh = 0; kh < 2; ++kh) {
            const int ks = kh * 8;
            uint32_t af[4][4], bf[8][2];
#pragma unroll
            for (int mi = 0; mi < 4; ++mi) {
                int r = wm + mi * 16 + lr;
                af[mi][0] = sm[AW(cur) + r * PAD + ks + lc];
                af[mi][1] = sm[AW(cur) + (r + 8) * PAD + ks + lc];
                af[mi][2] = sm[AW(cur) + r * PAD + ks + 4 + lc];
                af[mi][3] = sm[AW(cur) + (r + 8) * PAD + ks + 4 + lc];
            }
#pragma unroll
            for (int ni = 0; ni < 8; ++ni) {
                int r = wn + ni * 8 + lr;
                bf[ni][0] = sm[BW(cur) + r * PAD + ks + lc];
                bf[ni][1] = sm[BW(cur) + r * PAD + ks + 4 + lc];
            }
#pragma unroll
            for (int mi = 0; mi < 4; ++mi)
#pragma unroll
                for (int ni = 0; ni < 8; ++ni)
                    mma_tf32(acc[mi][ni], af[mi], bf[ni]);
        }
        if (s < 31) {
            const int nxt = (s + 1) & 1;
#pragma unroll
            for (int i = 0; i < 4; i++)
                *(uint4*)&sm[AW(nxt) + arow[i] * PAD + ac4[i] * 4] = cvt4(pa[i]);
#pragma unroll
            for (int i = 0; i < 2; i++)
                *(uint4*)&sm[BW(nxt) + brow[i] * PAD + bc4[i] * 4] = cvt4(pb[i]);
            __syncthreads();
        }
    }

    // epilogue: + b_proj[d] + q_flat[m, d]
#pragma unroll
    for (int mi = 0; mi < 4; ++mi) {
#pragma unroll
        for (int ni = 0; ni < 8; ++ni) {
            int d = d0 + wn + ni * 8 + 2 * lc;
            int h = (d >> 6) & 7, e = d & 63;
            float bp0 = bproj[d], bp1 = bproj[d + 1];
#pragma unroll
            for (int half = 0; half < 2; ++half) {
                int m = m0 + wm + mi * 16 + lr + half * 8;
                int n = m & 4095;
                const float* qp = &g_qkv[((size_t)(bb * HH + h) * NN + n) * HD + e];
                float* op = &out[(size_t)m * CC + d];
                op[0] = acc[mi][ni][half * 2 + 0] + bp0 + qp[0];
                op[1] = acc[mi][ni][half * 2 + 1] + bp1 + qp[1];
            }
        }
    }
}

// ---------------------------------------------------------------------------
// Kernel 2: attention pooling (unchanged, verified).
// ---------------------------------------------------------------------------
__global__ void __launch_bounds__(256) pool_kernel(const float* __restrict__ wh,
                                                   int pass2)
{
    __shared__ float logits[NN];
    __shared__ float ws[HD];
    __shared__ float red[8][HD];
    __shared__ float rscratch[8];

    const int bh = blockIdx.x;
    const int h  = bh & 7;
    const int tid  = threadIdx.x;
    const int lane = tid & 31;
    const int warp = tid >> 5;

    const float* src = g_qkv + (pass2 ? (size_t)BHNHD : 0) + (size_t)bh * NN * HD;
    float* gout = pass2 ? g_gk : g_gq;

    if (tid < HD) {
        float w = wh[h * HD + tid] * SCALE;
        if (pass2) w *= g_gq[bh * HD + tid];
        ws[tid] = w;
    }
    __syncthreads();

    float lmax = -1e30f;
    for (int n = warp; n < NN; n += 8) {
        const float* row = src + (size_t)n * HD;
        float v = row[lane] * ws[lane] + row[lane + 32] * ws[lane + 32];
#pragma unroll
        for (int o = 16; o; o >>= 1) v += __shfl_xor_sync(0xffffffffu, v, o);
        if (lane == 0) logits[n] = v;
        lmax = fmaxf(lmax, v);
    }
    if (lane == 0) rscratch[warp] = lmax;
    __syncthreads();
    if (tid == 0) {
        float m = rscratch[0];
        for (int i = 1; i < 8; i++) m = fmaxf(m, rscratch[i]);
        rscratch[0] = m;
    }
    __syncthreads();
    const float gmax = rscratch[0];
    __syncthreads();

    float lsum = 0.0f;
    for (int n = tid; n < NN; n += 256) {
        float e = expf(logits[n] - gmax);
        logits[n] = e;
        lsum += e;
    }
#pragma unroll
    for (int o = 16; o; o >>= 1) lsum += __shfl_xor_sync(0xffffffffu, lsum, o);
    if (lane == 0) rscratch[warp] = lsum;
    __syncthreads();
    if (tid == 0) {
        float s = 0.0f;
        for (int i = 0; i < 8; i++) s += rscratch[i];
        rscratch[0] = s;
    }
    __syncthreads();
    const float inv = 1.0f / rscratch[0];

    float a0 = 0.0f, a1 = 0.0f;
    for (int n = warp; n < NN; n += 8) {
        float p = logits[n];
        const float* row = src + (size_t)n * HD;
        a0 += p * row[lane];
        a1 += p * row[lane + 32];
    }
    red[warp][lane] = a0;
    red[warp][lane + 32] = a1;
    __syncthreads();
    if (tid < HD) {
        float s = 0.0f;
#pragma unroll
        for (int w = 0; w < 8; w++) s += red[w][tid];
        gout[bh * HD + tid] = s * inv;
    }
}

// ---------------------------------------------------------------------------
extern "C" void kernel_launch(void* const* d_in, const int* in_sizes, int n_in,
                              void* d_out, int out_size)
{
    const float* x      = (const float*)d_in[0];
    const float* w_qkv  = (const float*)d_in[1];
    const float* w_proj = (const float*)d_in[2];
    const float* b_proj = (const float*)d_in[3];
    const float* w_q    = (const float*)d_in[4];
    const float* w_k    = (const float*)d_in[5];
    float* out = (float*)d_out;

    static bool s_init = [] {
        cudaFuncSetAttribute(qkv_gemm_v2,
                             cudaFuncAttributeMaxDynamicSharedMemorySize, SMEM_QKV);
        cudaFuncSetAttribute(out_gemm_v2,
                             cudaFuncAttributeMaxDynamicSharedMemorySize, SMEM_OUT);
        return true;
    }();
    (void)s_init;

    qkv_gemm_v2<<<dim3(1536 / 128, 32768 / 256), 256, SMEM_QKV>>>(x, w_qkv);
    pool_kernel<<<BB * HH, 256>>>(w_q, 0);
    pool_kernel<<<BB * HH, 256>>>(w_k, 1);
    out_gemm_v2<<<dim3(512 / 128, 32768 / 256), 256, SMEM_OUT>>>(w_proj, b_proj, out);
}

// round 5
// speedup vs baseline: 2.6597x; 1.3250x over previous
#include <cuda_runtime.h>
#include <cuda_fp16.h>
#include <cstdint>

#define BB 8
#define NN 4096
#define CC 512
#define HH 8
#define HD 64
#define SCALE 0.125f
#define BHNHD (BB*HH*NN*HD)

#define RS 24          // smem row stride in halfs (16 k + 8 pad = 48B, conflict-free)

__device__ float g_qkv[3ull * BHNHD];
__device__ float g_gq[BB * HH * HD];
__device__ float g_gk[BB * HH * HD];

__device__ __forceinline__ uint32_t smem_u32(const void* p) {
    return (uint32_t)__cvta_generic_to_shared(p);
}
__device__ __forceinline__ uint2 f4toh4(float4 v) {
    __half2 lo = __floats2half2_rn(v.x, v.y);
    __half2 hi = __floats2half2_rn(v.z, v.w);
    uint2 r;
    r.x = *(uint32_t*)&lo;
    r.y = *(uint32_t*)&hi;
    return r;
}
__device__ __forceinline__ void ldm_x4(uint32_t* r, uint32_t addr) {
    asm volatile("ldmatrix.sync.aligned.m8n8.x4.shared.b16 {%0,%1,%2,%3}, [%4];"
        : "=r"(r[0]), "=r"(r[1]), "=r"(r[2]), "=r"(r[3]) : "r"(addr));
}
__device__ __forceinline__ void mma_f16(float* c, const uint32_t* a, const uint32_t* b) {
    asm volatile(
        "mma.sync.aligned.m16n8k16.row.col.f32.f16.f16.f32 "
        "{%0,%1,%2,%3},{%4,%5,%6,%7},{%8,%9},{%0,%1,%2,%3};"
        : "+f"(c[0]), "+f"(c[1]), "+f"(c[2]), "+f"(c[3])
        : "r"(a[0]), "r"(a[1]), "r"(a[2]), "r"(a[3]), "r"(b[0]), "r"(b[1]));
}

// ---------------------------------------------------------------------------
// Kernel 1: QKV GEMM (fp16 mma.sync m16n8k16 + ldmatrix).
// qkv[m,d] = sum_c x[m,c]*w[d,c]; M=32768, D=1536, K=512.
// CTA 256x128, warp 64x64 (4m x 2n warps), k16 stages, double buffered.
// ---------------------------------------------------------------------------
__global__ void __launch_bounds__(256) qkv_gemm_h(const float* __restrict__ X,
                                                  const float* __restrict__ W)
{
    __shared__ __half As[2][256 * RS];   // 12 KB per buffer
    __shared__ __half Bs[2][128 * RS];   //  6 KB per buffer

    const int tid = threadIdx.x;
    const int m0 = blockIdx.y * 256;
    const int d0 = blockIdx.x * 128;

    // loader tasks: A = 4/thread, B = 2/thread (4 threads per row)
    int arow[4], ac4[4], brow[2], bc4[2];
    const float* Ap[4]; const float* Bp[2];
#pragma unroll
    for (int i = 0; i < 4; i++) {
        int id = i * 256 + tid;
        arow[i] = id >> 2; ac4[i] = id & 3;
        Ap[i] = X + (size_t)(m0 + arow[i]) * CC + ac4[i] * 4;
    }
#pragma unroll
    for (int i = 0; i < 2; i++) {
        int id = i * 256 + tid;
        brow[i] = id >> 2; bc4[i] = id & 3;
        Bp[i] = W + (size_t)(d0 + brow[i]) * CC + bc4[i] * 4;
    }

    const int lane = tid & 31;
    const int warp = tid >> 5;
    const int wm = (warp & 3) * 64;
    const int wn = (warp >> 2) * 64;
    const int lr = lane >> 2;
    const int lc = lane & 3;

    // ldmatrix source addresses (byte offsets within each buffer)
    const int a_r  = lane & 15;
    const int a_k  = (lane >> 4) * 8;
    const int b_r  = (lane & 7) + ((lane >> 4) * 8);
    const int b_k  = ((lane >> 3) & 1) * 8;
    uint32_t aAddr[2][4], bAddr[2][4];
#pragma unroll
    for (int buf = 0; buf < 2; buf++) {
#pragma unroll
        for (int mi = 0; mi < 4; mi++)
            aAddr[buf][mi] = smem_u32(&As[buf][(wm + mi * 16 + a_r) * RS + a_k]);
#pragma unroll
        for (int nj = 0; nj < 4; nj++)
            bAddr[buf][nj] = smem_u32(&Bs[buf][(wn + nj * 16 + b_r) * RS + b_k]);
    }

    float acc[4][8][4] = {};

    // stage 0
#pragma unroll
    for (int i = 0; i < 4; i++)
        *(uint2*)&As[0][arow[i] * RS + ac4[i] * 4] = f4toh4(*(const float4*)Ap[i]);
#pragma unroll
    for (int i = 0; i < 2; i++)
        *(uint2*)&Bs[0][brow[i] * RS + bc4[i] * 4] = f4toh4(*(const float4*)Bp[i]);
    __syncthreads();

    float4 pa[4], pb[2];
    for (int s = 0; s < 32; ++s) {
        const int cur = s & 1;
        if (s < 31) {
#pragma unroll
            for (int i = 0; i < 4; i++) pa[i] = *(const float4*)(Ap[i] + (s + 1) * 16);
#pragma unroll
            for (int i = 0; i < 2; i++) pb[i] = *(const float4*)(Bp[i] + (s + 1) * 16);
        }
        uint32_t af[4][4], bf[4][4];
#pragma unroll
        for (int mi = 0; mi < 4; mi++) ldm_x4(af[mi], aAddr[cur][mi]);
#pragma unroll
        for (int nj = 0; nj < 4; nj++) ldm_x4(bf[nj], bAddr[cur][nj]);
#pragma unroll
        for (int mi = 0; mi < 4; ++mi)
#pragma unroll
            for (int ni = 0; ni < 8; ++ni)
                mma_f16(acc[mi][ni], af[mi], &bf[ni >> 1][(ni & 1) * 2]);
        if (s < 31) {
            const int nxt = (s + 1) & 1;
#pragma unroll
            for (int i = 0; i < 4; i++)
                *(uint2*)&As[nxt][arow[i] * RS + ac4[i] * 4] = f4toh4(pa[i]);
#pragma unroll
            for (int i = 0; i < 2; i++)
                *(uint2*)&Bs[nxt][brow[i] * RS + bc4[i] * 4] = f4toh4(pb[i]);
            __syncthreads();
        }
    }

    // scatter epilogue into g_qkv[t][b][h][n][e]
#pragma unroll
    for (int mi = 0; mi < 4; ++mi) {
#pragma unroll
        for (int ni = 0; ni < 8; ++ni) {
            int d = d0 + wn + ni * 8 + 2 * lc;
            int t = d >> 9, h = (d >> 6) & 7, e = d & 63;
#pragma unroll
            for (int half = 0; half < 2; ++half) {
                int m = m0 + wm + mi * 16 + lr + half * 8;
                int b = m >> 12, n = m & 4095;
                float* p = &g_qkv[(((size_t)t * BB + b) * HH + h) * ((size_t)NN * HD)
                                  + (size_t)n * HD + e];
                p[0] = acc[mi][ni][half * 2 + 0];
                p[1] = acc[mi][ni][half * 2 + 1];
            }
        }
    }
}

// ---------------------------------------------------------------------------
// Kernel 3: output GEMM (fp16 mma + ldmatrix), fused u = gk (x) v loader,
// epilogue out = acc + b_proj + q.  M=32768, D=512, K=512.
// ---------------------------------------------------------------------------
__global__ void __launch_bounds__(256) out_gemm_h(const float* __restrict__ W,
                                                  const float* __restrict__ bproj,
                                                  float* __restrict__ out)
{
    __shared__ __half As[2][256 * RS];
    __shared__ __half Bs[2][128 * RS];
    __shared__ float gks[CC];

    const int tid = threadIdx.x;
    const int m0 = blockIdx.y * 256;
    const int d0 = blockIdx.x * 128;
    const int bb = m0 >> 12;
    const int n0 = m0 & 4095;

    if (tid < 128)
        *(float4*)&gks[tid * 4] = *(const float4*)&g_gk[bb * CC + tid * 4];

    int arow[4], ac4[4], brow[2], bc4[2];
    const float* Bp[2];
#pragma unroll
    for (int i = 0; i < 4; i++) {
        int id = i * 256 + tid;
        arow[i] = id >> 2; ac4[i] = id & 3;
    }
#pragma unroll
    for (int i = 0; i < 2; i++) {
        int id = i * 256 + tid;
        brow[i] = id >> 2; bc4[i] = id & 3;
        Bp[i] = W + (size_t)(d0 + brow[i]) * CC + bc4[i] * 4;
    }

    const float* vbase = g_qkv + 2ull * BHNHD;
    const int lane = tid & 31;
    const int warp = tid >> 5;
    const int wm = (warp & 3) * 64;
    const int wn = (warp >> 2) * 64;
    const int lr = lane >> 2;
    const int lc = lane & 3;

    const int a_r = lane & 15;
    const int a_k = (lane >> 4) * 8;
    const int b_r = (lane & 7) + ((lane >> 4) * 8);
    const int b_k = ((lane >> 3) & 1) * 8;
    uint32_t aAddr[2][4], bAddr[2][4];
#pragma unroll
    for (int buf = 0; buf < 2; buf++) {
#pragma unroll
        for (int mi = 0; mi < 4; mi++)
            aAddr[buf][mi] = smem_u32(&As[buf][(wm + mi * 16 + a_r) * RS + a_k]);
#pragma unroll
        for (int nj = 0; nj < 4; nj++)
            bAddr[buf][nj] = smem_u32(&Bs[buf][(wn + nj * 16 + b_r) * RS + b_k]);
    }

    float acc[4][8][4] = {};
    __syncthreads();   // gks visible

    // fused A loader: u[m, c] = gk[c] * v[b, c>>6, n, c&63]
    auto loadA = [&](int s, int i) -> float4 {
        int c = s * 16 + ac4[i] * 4;
        int h = c >> 6, e = c & 63;
        float4 v = *(const float4*)(vbase
            + ((size_t)(bb * HH + h) * NN + n0 + arow[i]) * HD + e);
        float4 g = *(const float4*)&gks[c];
        return make_float4(v.x * g.x, v.y * g.y, v.z * g.z, v.w * g.w);
    };

#pragma unroll
    for (int i = 0; i < 4; i++)
        *(uint2*)&As[0][arow[i] * RS + ac4[i] * 4] = f4toh4(loadA(0, i));
#pragma unroll
    for (int i = 0; i < 2; i++)
        *(uint2*)&Bs[0][brow[i] * RS + bc4[i] * 4] = f4toh4(*(const float4*)Bp[i]);
    __syncthreads();

    float4 pa[4], pb[2];
    for (int s = 0; s < 32; ++s) {
        const int cur = s & 1;
        if (s < 31) {
#pragma unroll
            for (int i = 0; i < 4; i++) pa[i] = loadA(s + 1, i);
#pragma unroll
            for (int i = 0; i < 2; i++) pb[i] = *(const float4*)(Bp[i] + (s + 1) * 16);
        }
        uint32_t af[4][4], bf[4][4];
#pragma unroll
        for (int mi = 0; mi < 4; mi++) ldm_x4(af[mi], aAddr[cur][mi]);
#pragma unroll
        for (int nj = 0; nj < 4; nj++) ldm_x4(bf[nj], bAddr[cur][nj]);
#pragma unroll
        for (int mi = 0; mi < 4; ++mi)
#pragma unroll
            for (int ni = 0; ni < 8; ++ni)
                mma_f16(acc[mi][ni], af[mi], &bf[ni >> 1][(ni & 1) * 2]);
        if (s < 31) {
            const int nxt = (s + 1) & 1;
#pragma unroll
            for (int i = 0; i < 4; i++)
                *(uint2*)&As[nxt][arow[i] * RS + ac4[i] * 4] = f4toh4(pa[i]);
#pragma unroll
            for (int i = 0; i < 2; i++)
                *(uint2*)&Bs[nxt][brow[i] * RS + bc4[i] * 4] = f4toh4(pb[i]);
            __syncthreads();
        }
    }

    // epilogue: + b_proj[d] + q_flat[m, d]
#pragma unroll
    for (int mi = 0; mi < 4; ++mi) {
#pragma unroll
        for (int ni = 0; ni < 8; ++ni) {
            int d = d0 + wn + ni * 8 + 2 * lc;
            int h = (d >> 6) & 7, e = d & 63;
            float bp0 = bproj[d], bp1 = bproj[d + 1];
#pragma unroll
            for (int half = 0; half < 2; ++half) {
                int m = m0 + wm + mi * 16 + lr + half * 8;
                int n = m & 4095;
                const float* qp = &g_qkv[((size_t)(bb * HH + h) * NN + n) * HD + e];
                float* op = &out[(size_t)m * CC + d];
                op[0] = acc[mi][ni][half * 2 + 0] + bp0 + qp[0];
                op[1] = acc[mi][ni][half * 2 + 1] + bp1 + qp[1];
            }
        }
    }
}

// ---------------------------------------------------------------------------
// Kernel 2: attention pooling (unchanged, verified).
// ---------------------------------------------------------------------------
__global__ void __launch_bounds__(256) pool_kernel(const float* __restrict__ wh,
                                                   int pass2)
{
    __shared__ float logits[NN];
    __shared__ float ws[HD];
    __shared__ float red[8][HD];
    __shared__ float rscratch[8];

    const int bh = blockIdx.x;
    const int h  = bh & 7;
    const int tid  = threadIdx.x;
    const int lane = tid & 31;
    const int warp = tid >> 5;

    const float* src = g_qkv + (pass2 ? (size_t)BHNHD : 0) + (size_t)bh * NN * HD;
    float* gout = pass2 ? g_gk : g_gq;

    if (tid < HD) {
        float w = wh[h * HD + tid] * SCALE;
        if (pass2) w *= g_gq[bh * HD + tid];
        ws[tid] = w;
    }
    __syncthreads();

    float lmax = -1e30f;
    for (int n = warp; n < NN; n += 8) {
        const float* row = src + (size_t)n * HD;
        float v = row[lane] * ws[lane] + row[lane + 32] * ws[lane + 32];
#pragma unroll
        for (int o = 16; o; o >>= 1) v += __shfl_xor_sync(0xffffffffu, v, o);
        if (lane == 0) logits[n] = v;
        lmax = fmaxf(lmax, v);
    }
    if (lane == 0) rscratch[warp] = lmax;
    __syncthreads();
    if (tid == 0) {
        float m = rscratch[0];
        for (int i = 1; i < 8; i++) m = fmaxf(m, rscratch[i]);
        rscratch[0] = m;
    }
    __syncthreads();
    const float gmax = rscratch[0];
    __syncthreads();

    float lsum = 0.0f;
    for (int n = tid; n < NN; n += 256) {
        float e = expf(logits[n] - gmax);
        logits[n] = e;
        lsum += e;
    }
#pragma unroll
    for (int o = 16; o; o >>= 1) lsum += __shfl_xor_sync(0xffffffffu, lsum, o);
    if (lane == 0) rscratch[warp] = lsum;
    __syncthreads();
    if (tid == 0) {
        float s = 0.0f;
        for (int i = 0; i < 8; i++) s += rscratch[i];
        rscratch[0] = s;
    }
    __syncthreads();
    const float inv = 1.0f / rscratch[0];

    float a0 = 0.0f, a1 = 0.0f;
    for (int n = warp; n < NN; n += 8) {
        float p = logits[n];
        const float* row = src + (size_t)n * HD;
        a0 += p * row[lane];
        a1 += p * row[lane + 32];
    }
    red[warp][lane] = a0;
    red[warp][lane + 32] = a1;
    __syncthreads();
    if (tid < HD) {
        float s = 0.0f;
#pragma unroll
        for (int w = 0; w < 8; w++) s += red[w][tid];
        gout[bh * HD + tid] = s * inv;
    }
}

// ---------------------------------------------------------------------------
extern "C" void kernel_launch(void* const* d_in, const int* in_sizes, int n_in,
                              void* d_out, int out_size)
{
    const float* x      = (const float*)d_in[0];
    const float* w_qkv  = (const float*)d_in[1];
    const float* w_proj = (const float*)d_in[2];
    const float* b_proj = (const float*)d_in[3];
    const float* w_q    = (const float*)d_in[4];
    const float* w_k    = (const float*)d_in[5];
    float* out = (float*)d_out;

    qkv_gemm_h<<<dim3(1536 / 128, 32768 / 256), 256>>>(x, w_qkv);
    pool_kernel<<<BB * HH, 256>>>(w_q, 0);
    pool_kernel<<<BB * HH, 256>>>(w_k, 1);
    out_gemm_h<<<dim3(512 / 128, 32768 / 256), 256>>>(w_proj, b_proj, out);
}

// round 6
// speedup vs baseline: 3.2620x; 1.2264x over previous
#include <cuda_runtime.h>
#include <cuda_fp16.h>
#include <cstdint>

#define BB 8
#define NN 4096
#define CC 512
#define HH 8
#define HD 64
#define SCALE 0.125f
#define BHNHD (BB*HH*NN*HD)

#define RS 24          // smem row stride in halfs (16 k + 8 pad = 48B, conflict-free)
#define ABUF_B (256 * RS * 2)   // bytes per A buffer
#define BBUF_B (128 * RS * 2)   // bytes per B buffer

__device__ float g_qkv[3ull * BHNHD];
__device__ float g_gq[BB * HH * HD];
__device__ float g_gk[BB * HH * HD];

__device__ __forceinline__ uint32_t smem_u32(const void* p) {
    return (uint32_t)__cvta_generic_to_shared(p);
}
__device__ __forceinline__ uint2 f4toh4(float4 v) {
    __half2 lo = __floats2half2_rn(v.x, v.y);
    __half2 hi = __floats2half2_rn(v.z, v.w);
    uint2 r;
    r.x = *(uint32_t*)&lo;
    r.y = *(uint32_t*)&hi;
    return r;
}
__device__ __forceinline__ void ldm_x4(uint32_t* r, uint32_t addr) {
    asm volatile("ldmatrix.sync.aligned.m8n8.x4.shared.b16 {%0,%1,%2,%3}, [%4];"
        : "=r"(r[0]), "=r"(r[1]), "=r"(r[2]), "=r"(r[3]) : "r"(addr));
}
__device__ __forceinline__ void mma_f16(float* c, const uint32_t* a, const uint32_t* b) {
    asm volatile(
        "mma.sync.aligned.m16n8k16.row.col.f32.f16.f16.f32 "
        "{%0,%1,%2,%3},{%4,%5,%6,%7},{%8,%9},{%0,%1,%2,%3};"
        : "+f"(c[0]), "+f"(c[1]), "+f"(c[2]), "+f"(c[3])
        : "r"(a[0]), "r"(a[1]), "r"(a[2]), "r"(a[3]), "r"(b[0]), "r"(b[1]));
}

// ---------------------------------------------------------------------------
// Kernel 1: QKV GEMM (fp16 mma m16n8k16 + ldmatrix), 512 threads.
// qkv[m,d] = sum_c x[m,c]*w[d,c]; M=32768, D=1536, K=512.
// CTA 256x128, 16 warps (4m x 4n), warp tile 64x32, double-buffered k16.
// ---------------------------------------------------------------------------
__global__ void __launch_bounds__(512) qkv_gemm_h(const float* __restrict__ X,
                                                  const float* __restrict__ W)
{
    __shared__ __half As[2][256 * RS];   // 24 KB
    __shared__ __half Bs[2][128 * RS];   // 12 KB

    const int tid = threadIdx.x;
    const int m0 = blockIdx.y * 256;
    const int d0 = blockIdx.x * 128;

    // loader tasks: A = 2/thread, B = 1/thread (4 threads per row of 16 floats)
    int arow[2], ac4[2];
    const float* Ap[2];
#pragma unroll
    for (int i = 0; i < 2; i++) {
        int id = i * 512 + tid;
        arow[i] = id >> 2; ac4[i] = id & 3;
        Ap[i] = X + (size_t)(m0 + arow[i]) * CC + ac4[i] * 4;
    }
    const int brow = tid >> 2, bc4 = tid & 3;
    const float* Bp = W + (size_t)(d0 + brow) * CC + bc4 * 4;

    const int lane = tid & 31;
    const int warp = tid >> 5;
    const int wm = (warp & 3) * 64;
    const int wn = (warp >> 2) * 32;
    const int lr = lane >> 2;
    const int lc = lane & 3;

    // ldmatrix base addresses (buffer 0); buffer 1 = +ABUF_B / +BBUF_B
    const int a_r = lane & 15;
    const int a_k = (lane >> 4) * 8;
    const int b_r = (lane & 7) + ((lane >> 4) * 8);
    const int b_k = ((lane >> 3) & 1) * 8;
    uint32_t aAddr[4], bAddr[2];
#pragma unroll
    for (int mi = 0; mi < 4; mi++)
        aAddr[mi] = smem_u32(&As[0][(wm + mi * 16 + a_r) * RS + a_k]);
#pragma unroll
    for (int nj = 0; nj < 2; nj++)
        bAddr[nj] = smem_u32(&Bs[0][(wn + nj * 16 + b_r) * RS + b_k]);

    float acc[4][4][4] = {};

    // stage 0
#pragma unroll
    for (int i = 0; i < 2; i++)
        *(uint2*)&As[0][arow[i] * RS + ac4[i] * 4] = f4toh4(*(const float4*)Ap[i]);
    *(uint2*)&Bs[0][brow * RS + bc4 * 4] = f4toh4(*(const float4*)Bp);
    __syncthreads();

    float4 pa[2], pb;
    for (int s = 0; s < 32; ++s) {
        const int cur = s & 1;
        if (s < 31) {
#pragma unroll
            for (int i = 0; i < 2; i++) pa[i] = *(const float4*)(Ap[i] + (s + 1) * 16);
            pb = *(const float4*)(Bp + (s + 1) * 16);
        }
        uint32_t af[4][4], bf[2][4];
#pragma unroll
        for (int mi = 0; mi < 4; mi++) ldm_x4(af[mi], aAddr[mi] + cur * ABUF_B);
#pragma unroll
        for (int nj = 0; nj < 2; nj++) ldm_x4(bf[nj], bAddr[nj] + cur * BBUF_B);
#pragma unroll
        for (int mi = 0; mi < 4; ++mi)
#pragma unroll
            for (int ni = 0; ni < 4; ++ni)
                mma_f16(acc[mi][ni], af[mi], &bf[ni >> 1][(ni & 1) * 2]);
        if (s < 31) {
            const int nxt = (s + 1) & 1;
#pragma unroll
            for (int i = 0; i < 2; i++)
                *(uint2*)&As[nxt][arow[i] * RS + ac4[i] * 4] = f4toh4(pa[i]);
            *(uint2*)&Bs[nxt][brow * RS + bc4 * 4] = f4toh4(pb);
            __syncthreads();
        }
    }

    // scatter epilogue into g_qkv[t][b][h][n][e]
#pragma unroll
    for (int mi = 0; mi < 4; ++mi) {
#pragma unroll
        for (int ni = 0; ni < 4; ++ni) {
            int d = d0 + wn + ni * 8 + 2 * lc;
            int t = d >> 9, h = (d >> 6) & 7, e = d & 63;
#pragma unroll
            for (int half = 0; half < 2; ++half) {
                int m = m0 + wm + mi * 16 + lr + half * 8;
                int b = m >> 12, n = m & 4095;
                float* p = &g_qkv[(((size_t)t * BB + b) * HH + h) * ((size_t)NN * HD)
                                  + (size_t)n * HD + e];
                p[0] = acc[mi][ni][half * 2 + 0];
                p[1] = acc[mi][ni][half * 2 + 1];
            }
        }
    }
}

// ---------------------------------------------------------------------------
// Kernel 3: output GEMM (fp16 mma + ldmatrix), 512 threads, fused
// u = gk (x) v loader, epilogue out = acc + b_proj + q. M=32768, D=512, K=512.
// ---------------------------------------------------------------------------
__global__ void __launch_bounds__(512) out_gemm_h(const float* __restrict__ W,
                                                  const float* __restrict__ bproj,
                                                  float* __restrict__ out)
{
    __shared__ __half As[2][256 * RS];
    __shared__ __half Bs[2][128 * RS];
    __shared__ float gks[CC];

    const int tid = threadIdx.x;
    const int m0 = blockIdx.y * 256;
    const int d0 = blockIdx.x * 128;
    const int bb = m0 >> 12;
    const int n0 = m0 & 4095;

    if (tid < 128)
        *(float4*)&gks[tid * 4] = *(const float4*)&g_gk[bb * CC + tid * 4];

    int arow[2], ac4[2];
#pragma unroll
    for (int i = 0; i < 2; i++) {
        int id = i * 512 + tid;
        arow[i] = id >> 2; ac4[i] = id & 3;
    }
    const int brow = tid >> 2, bc4 = tid & 3;
    const float* Bp = W + (size_t)(d0 + brow) * CC + bc4 * 4;

    const float* vbase = g_qkv + 2ull * BHNHD;
    const int lane = tid & 31;
    const int warp = tid >> 5;
    const int wm = (warp & 3) * 64;
    const int wn = (warp >> 2) * 32;
    const int lr = lane >> 2;
    const int lc = lane & 3;

    const int a_r = lane & 15;
    const int a_k = (lane >> 4) * 8;
    const int b_r = (lane & 7) + ((lane >> 4) * 8);
    const int b_k = ((lane >> 3) & 1) * 8;
    uint32_t aAddr[4], bAddr[2];
#pragma unroll
    for (int mi = 0; mi < 4; mi++)
        aAddr[mi] = smem_u32(&As[0][(wm + mi * 16 + a_r) * RS + a_k]);
#pragma unroll
    for (int nj = 0; nj < 2; nj++)
        bAddr[nj] = smem_u32(&Bs[0][(wn + nj * 16 + b_r) * RS + b_k]);

    float acc[4][4][4] = {};
    __syncthreads();   // gks visible

    // fused A loader: u[m, c] = gk[c] * v[b, c>>6, n, c&63]
    auto loadA = [&](int s, int i) -> float4 {
        int c = s * 16 + ac4[i] * 4;
        int h = c >> 6, e = c & 63;
        float4 v = *(const float4*)(vbase
            + ((size_t)(bb * HH + h) * NN + n0 + arow[i]) * HD + e);
        float4 g = *(const float4*)&gks[c];
        return make_float4(v.x * g.x, v.y * g.y, v.z * g.z, v.w * g.w);
    };

#pragma unroll
    for (int i = 0; i < 2; i++)
        *(uint2*)&As[0][arow[i] * RS + ac4[i] * 4] = f4toh4(loadA(0, i));
    *(uint2*)&Bs[0][brow * RS + bc4 * 4] = f4toh4(*(const float4*)Bp);
    __syncthreads();

    float4 pa[2], pb;
    for (int s = 0; s < 32; ++s) {
        const int cur = s & 1;
        if (s < 31) {
#pragma unroll
            for (int i = 0; i < 2; i++) pa[i] = loadA(s + 1, i);
            pb = *(const float4*)(Bp + (s + 1) * 16);
        }
        uint32_t af[4][4], bf[2][4];
#pragma unroll
        for (int mi = 0; mi < 4; mi++) ldm_x4(af[mi], aAddr[mi] + cur * ABUF_B);
#pragma unroll
        for (int nj = 0; nj < 2; nj++) ldm_x4(bf[nj], bAddr[nj] + cur * BBUF_B);
#pragma unroll
        for (int mi = 0; mi < 4; ++mi)
#pragma unroll
            for (int ni = 0; ni < 4; ++ni)
                mma_f16(acc[mi][ni], af[mi], &bf[ni >> 1][(ni & 1) * 2]);
        if (s < 31) {
            const int nxt = (s + 1) & 1;
#pragma unroll
            for (int i = 0; i < 2; i++)
                *(uint2*)&As[nxt][arow[i] * RS + ac4[i] * 4] = f4toh4(pa[i]);
            *(uint2*)&Bs[nxt][brow * RS + bc4 * 4] = f4toh4(pb);
            __syncthreads();
        }
    }

    // epilogue: + b_proj[d] + q_flat[m, d]
#pragma unroll
    for (int mi = 0; mi < 4; ++mi) {
#pragma unroll
        for (int ni = 0; ni < 4; ++ni) {
            int d = d0 + wn + ni * 8 + 2 * lc;
            int h = (d >> 6) & 7, e = d & 63;
            float bp0 = bproj[d], bp1 = bproj[d + 1];
#pragma unroll
            for (int half = 0; half < 2; ++half) {
                int m = m0 + wm + mi * 16 + lr + half * 8;
                int n = m & 4095;
                const float* qp = &g_qkv[((size_t)(bb * HH + h) * NN + n) * HD + e];
                float* op = &out[(size_t)m * CC + d];
                op[0] = acc[mi][ni][half * 2 + 0] + bp0 + qp[0];
                op[1] = acc[mi][ni][half * 2 + 1] + bp1 + qp[1];
            }
        }
    }
}

// ---------------------------------------------------------------------------
// Kernel 2: attention pooling, 512 threads (16 row-warps).
// ---------------------------------------------------------------------------
__global__ void __launch_bounds__(512) pool_kernel(const float* __restrict__ wh,
                                                   int pass2)
{
    __shared__ float logits[NN];
    __shared__ float ws[HD];
    __shared__ float red[16][HD];
    __shared__ float rscratch[16];

    const int bh = blockIdx.x;
    const int h  = bh & 7;
    const int tid  = threadIdx.x;
    const int lane = tid & 31;
    const int warp = tid >> 5;

    const float* src = g_qkv + (pass2 ? (size_t)BHNHD : 0) + (size_t)bh * NN * HD;
    float* gout = pass2 ? g_gk : g_gq;

    if (tid < HD) {
        float w = wh[h * HD + tid] * SCALE;
        if (pass2) w *= g_gq[bh * HD + tid];
        ws[tid] = w;
    }
    __syncthreads();

    float lmax = -1e30f;
    for (int n = warp; n < NN; n += 16) {
        const float* row = src + (size_t)n * HD;
        float v = row[lane] * ws[lane] + row[lane + 32] * ws[lane + 32];
#pragma unroll
        for (int o = 16; o; o >>= 1) v += __shfl_xor_sync(0xffffffffu, v, o);
        if (lane == 0) logits[n] = v;
        lmax = fmaxf(lmax, v);
    }
    if (lane == 0) rscratch[warp] = lmax;
    __syncthreads();
    if (tid == 0) {
        float m = rscratch[0];
        for (int i = 1; i < 16; i++) m = fmaxf(m, rscratch[i]);
        rscratch[0] = m;
    }
    __syncthreads();
    const float gmax = rscratch[0];
    __syncthreads();

    float lsum = 0.0f;
    for (int n = tid; n < NN; n += 512) {
        float e = expf(logits[n] - gmax);
        logits[n] = e;
        lsum += e;
    }
#pragma unroll
    for (int o = 16; o; o >>= 1) lsum += __shfl_xor_sync(0xffffffffu, lsum, o);
    if (lane == 0) rscratch[warp] = lsum;
    __syncthreads();
    if (tid == 0) {
        float s = 0.0f;
        for (int i = 0; i < 16; i++) s += rscratch[i];
        rscratch[0] = s;
    }
    __syncthreads();
    const float inv = 1.0f / rscratch[0];

    float a0 = 0.0f, a1 = 0.0f;
    for (int n = warp; n < NN; n += 16) {
        float p = logits[n];
        const float* row = src + (size_t)n * HD;
        a0 += p * row[lane];
        a1 += p * row[lane + 32];
    }
    red[warp][lane] = a0;
    red[warp][lane + 32] = a1;
    __syncthreads();
    if (tid < HD) {
        float s = 0.0f;
#pragma unroll
        for (int w = 0; w < 16; w++) s += red[w][tid];
        gout[bh * HD + tid] = s * inv;
    }
}

// ---------------------------------------------------------------------------
extern "C" void kernel_launch(void* const* d_in, const int* in_sizes, int n_in,
                              void* d_out, int out_size)
{
    const float* x      = (const float*)d_in[0];
    const float* w_qkv  = (const float*)d_in[1];
    const float* w_proj = (const float*)d_in[2];
    const float* b_proj = (const float*)d_in[3];
    const float* w_q    = (const float*)d_in[4];
    const float* w_k    = (const float*)d_in[5];
    float* out = (float*)d_out;

    qkv_gemm_h<<<dim3(1536 / 128, 32768 / 256), 512>>>(x, w_qkv);
    pool_kernel<<<BB * HH, 512>>>(w_q, 0);
    pool_kernel<<<BB * HH, 512>>>(w_k, 1);
    out_gemm_h<<<dim3(512 / 128, 32768 / 256), 512>>>(w_proj, b_proj, out);
}

// round 7
// speedup vs baseline: 4.0937x; 1.2550x over previous
#include <cuda_runtime.h>
#include <cuda_fp16.h>
#include <cstdint>

#define BB 8
#define NN 4096
#define CC 512
#define HH 8
#define HD 64
#define SCALE 0.125f
#define BHNHD (BB*HH*NN*HD)

#define RS 24                     // smem row stride in halfs (48B, 16B-aligned)
#define ABUF (256 * RS * 2)       // bytes per A stage buffer (12 KB)
#define BBUF (128 * RS * 2)       // bytes per B stage buffer (6 KB)
#define SMEM_GEMM (4 * (ABUF + BBUF))   // 72 KB (4-stage pipeline)

__device__ __half g_qkv[3ull * BHNHD];     // q,k,v fp16
__device__ __half g_xh[(size_t)BB * NN * CC];
__device__ __half g_w1h[3 * CC * CC];
__device__ __half g_w2h[CC * CC];
__device__ float  g_gq[BB * HH * HD];
__device__ float  g_gk[BB * HH * HD];

__device__ __forceinline__ uint32_t smem_u32(const void* p) {
    return (uint32_t)__cvta_generic_to_shared(p);
}
__device__ __forceinline__ void cp16(uint32_t dst, const void* src) {
    asm volatile("cp.async.cg.shared.global [%0], [%1], 16;"
        :: "r"(dst), "l"(src) : "memory");
}
#define CP_COMMIT() asm volatile("cp.async.commit_group;" ::: "memory")
#define CP_WAIT2()  asm volatile("cp.async.wait_group 2;" ::: "memory")

__device__ __forceinline__ void ldm_x4(uint32_t* r, uint32_t addr) {
    asm volatile("ldmatrix.sync.aligned.m8n8.x4.shared.b16 {%0,%1,%2,%3}, [%4];"
        : "=r"(r[0]), "=r"(r[1]), "=r"(r[2]), "=r"(r[3]) : "r"(addr));
}
__device__ __forceinline__ void mma_f16(float* c, const uint32_t* a, const uint32_t* b) {
    asm volatile(
        "mma.sync.aligned.m16n8k16.row.col.f32.f16.f16.f32 "
        "{%0,%1,%2,%3},{%4,%5,%6,%7},{%8,%9},{%0,%1,%2,%3};"
        : "+f"(c[0]), "+f"(c[1]), "+f"(c[2]), "+f"(c[3])
        : "r"(a[0]), "r"(a[1]), "r"(a[2]), "r"(a[3]), "r"(b[0]), "r"(b[1]));
}

// ---------------------------------------------------------------------------
// f32 -> f16 convert (grid-stride, float4 granularity)
// ---------------------------------------------------------------------------
__global__ void f2h_kernel(const float* __restrict__ src, __half* __restrict__ dst,
                           int n4)
{
    for (int i = blockIdx.x * blockDim.x + threadIdx.x; i < n4;
         i += gridDim.x * blockDim.x) {
        float4 v = *(const float4*)(src + (size_t)i * 4);
        __half2 lo = __floats2half2_rn(v.x, v.y);
        __half2 hi = __floats2half2_rn(v.z, v.w);
        uint2 p; p.x = *(uint32_t*)&lo; p.y = *(uint32_t*)&hi;
        *(uint2*)(dst + (size_t)i * 4) = p;
    }
}

// ---------------------------------------------------------------------------
// Kernel 1: QKV GEMM (fp16 mma + ldmatrix + 4-stage cp.async).
// qkv[m,d] = sum_c x[m,c]*w[d,c]; M=32768, D=1536, K=512.
// CTA 256x128, 16 warps (4m x 4n), warp tile 64x32.
// ---------------------------------------------------------------------------
__global__ void __launch_bounds__(512) qkv_gemm_h(const __half* __restrict__ Xh,
                                                  const __half* __restrict__ Wh)
{
    extern __shared__ __half sm[];
    __half* As = sm;                    // 4 bufs x 256*RS
    __half* Bs = sm + 4 * 256 * RS;     // 4 bufs x 128*RS

    const int tid = threadIdx.x;
    const int m0 = blockIdx.y * 256;
    const int d0 = blockIdx.x * 128;

    // cp.async tasks: A 1 x 16B / thread, B 1 x 16B for tid<256
    const int ar = tid >> 1, ach = tid & 1;
    const __half* Agp = Xh + (size_t)(m0 + ar) * CC + ach * 8;
    const uint32_t Asm = smem_u32(As + ar * RS + ach * 8);
    const int br = (tid & 255) >> 1, bch = tid & 1;
    const __half* Bgp = Wh + (size_t)(d0 + br) * CC + bch * 8;
    const uint32_t Bsm = smem_u32(Bs + br * RS + bch * 8);

    auto issue = [&](int s) {
        const int buf = s & 3;
        cp16(Asm + buf * ABUF, Agp + s * 16);
        if (tid < 256) cp16(Bsm + buf * BBUF, Bgp + s * 16);
    };

    const int lane = tid & 31;
    const int warp = tid >> 5;
    const int wm = (warp & 3) * 64;
    const int wn = (warp >> 2) * 32;
    const int lr = lane >> 2;
    const int lc = lane & 3;

    const int a_r = lane & 15, a_k = (lane >> 4) * 8;
    const int b_r = (lane & 7) + ((lane >> 4) * 8), b_k = ((lane >> 3) & 1) * 8;
    uint32_t aAddr[4], bAddr[2];
#pragma unroll
    for (int mi = 0; mi < 4; mi++)
        aAddr[mi] = smem_u32(&As[(wm + mi * 16 + a_r) * RS + a_k]);
#pragma unroll
    for (int nj = 0; nj < 2; nj++)
        bAddr[nj] = smem_u32(&Bs[(wn + nj * 16 + b_r) * RS + b_k]);

    float acc[4][4][4] = {};

    issue(0); CP_COMMIT();
    issue(1); CP_COMMIT();
    issue(2); CP_COMMIT();

    for (int s = 0; s < 32; ++s) {
        CP_WAIT2();
        __syncthreads();
        if (s + 3 < 32) issue(s + 3);
        CP_COMMIT();
        const int cur = s & 3;
        uint32_t af[4][4], bf[2][4];
#pragma unroll
        for (int mi = 0; mi < 4; mi++) ldm_x4(af[mi], aAddr[mi] + cur * ABUF);
#pragma unroll
        for (int nj = 0; nj < 2; nj++) ldm_x4(bf[nj], bAddr[nj] + cur * BBUF);
#pragma unroll
        for (int mi = 0; mi < 4; ++mi)
#pragma unroll
            for (int ni = 0; ni < 4; ++ni)
                mma_f16(acc[mi][ni], af[mi], &bf[ni >> 1][(ni & 1) * 2]);
    }

    // scatter epilogue into g_qkv[t][b][h][n][e]  (fp16)
#pragma unroll
    for (int mi = 0; mi < 4; ++mi) {
#pragma unroll
        for (int ni = 0; ni < 4; ++ni) {
            int d = d0 + wn + ni * 8 + 2 * lc;
            int t = d >> 9, h = (d >> 6) & 7, e = d & 63;
#pragma unroll
            for (int half = 0; half < 2; ++half) {
                int m = m0 + wm + mi * 16 + lr + half * 8;
                int b = m >> 12, n = m & 4095;
                __half2 hv = __floats2half2_rn(acc[mi][ni][half * 2 + 0],
                                               acc[mi][ni][half * 2 + 1]);
                *(__half2*)&g_qkv[(((size_t)t * BB + b) * HH + h) * ((size_t)NN * HD)
                                  + (size_t)n * HD + e] = hv;
            }
        }
    }
}

// ---------------------------------------------------------------------------
// Kernel 3: output GEMM. A = v (fp16, cp.async raw), gk multiply applied on
// A fragments post-ldmatrix. Epilogue out = acc + b_proj + q(fp16).
// M=32768, D=512, K=512.
// ---------------------------------------------------------------------------
__global__ void __launch_bounds__(512) out_gemm_h(const __half* __restrict__ Wh,
                                                  const float* __restrict__ bproj,
                                                  float* __restrict__ out)
{
    extern __shared__ __half sm[];
    __half* As = sm;
    __half* Bs = sm + 4 * 256 * RS;
    __shared__ __half2 gkh[CC / 2];

    const int tid = threadIdx.x;
    const int m0 = blockIdx.y * 256;
    const int d0 = blockIdx.x * 128;
    const int bb = m0 >> 12;
    const int n0 = m0 & 4095;

    if (tid < 256) {
        float2 g = *(const float2*)&g_gk[bb * CC + tid * 2];
        gkh[tid] = __floats2half2_rn(g.x, g.y);
    }

    const __half* vbase = g_qkv + 2ull * BHNHD;

    // A loader: row n = tid>>1 (0..255), chunk = tid&1 covers 8 halfs of c
    const int ar = tid >> 1, ach = tid & 1;
    const uint32_t Asm = smem_u32(As + ar * RS + ach * 8);
    const int br = (tid & 255) >> 1, bch = tid & 1;
    const __half* Bgp = Wh + (size_t)(d0 + br) * CC + bch * 8;
    const uint32_t Bsm = smem_u32(Bs + br * RS + bch * 8);

    auto issue = [&](int s) {
        const int buf = s & 3;
        const int c = s * 16 + ach * 8;
        const int h = c >> 6, e = c & 63;
        cp16(Asm + buf * ABUF,
             vbase + ((size_t)(bb * HH + h) * NN + n0 + ar) * HD + e);
        if (tid < 256) cp16(Bsm + buf * BBUF, Bgp + s * 16);
    };

    const int lane = tid & 31;
    const int warp = tid >> 5;
    const int wm = (warp & 3) * 64;
    const int wn = (warp >> 2) * 32;
    const int lr = lane >> 2;
    const int lc = lane & 3;

    const int a_r = lane & 15, a_k = (lane >> 4) * 8;
    const int b_r = (lane & 7) + ((lane >> 4) * 8), b_k = ((lane >> 3) & 1) * 8;
    uint32_t aAddr[4], bAddr[2];
#pragma unroll
    for (int mi = 0; mi < 4; mi++)
        aAddr[mi] = smem_u32(&As[(wm + mi * 16 + a_r) * RS + a_k]);
#pragma unroll
    for (int nj = 0; nj < 2; nj++)
        bAddr[nj] = smem_u32(&Bs[(wn + nj * 16 + b_r) * RS + b_k]);

    float acc[4][4][4] = {};
    __syncthreads();   // gkh visible

    issue(0); CP_COMMIT();
    issue(1); CP_COMMIT();
    issue(2); CP_COMMIT();

    for (int s = 0; s < 32; ++s) {
        CP_WAIT2();
        __syncthreads();
        if (s + 3 < 32) issue(s + 3);
        CP_COMMIT();
        const int cur = s & 3;
        // gk factors for this k-chunk: regs 0/1 at c = s*16 + lc*2, regs 2/3 at +8
        const __half2 glo = gkh[s * 8 + lc];
        const __half2 ghi = gkh[s * 8 + 4 + lc];
        uint32_t af[4][4], bf[2][4];
#pragma unroll
        for (int mi = 0; mi < 4; mi++) {
            ldm_x4(af[mi], aAddr[mi] + cur * ABUF);
            __half2* a2 = (__half2*)af[mi];
            a2[0] = __hmul2(a2[0], glo);
            a2[1] = __hmul2(a2[1], glo);
            a2[2] = __hmul2(a2[2], ghi);
            a2[3] = __hmul2(a2[3], ghi);
        }
#pragma unroll
        for (int nj = 0; nj < 2; nj++) ldm_x4(bf[nj], bAddr[nj] + cur * BBUF);
#pragma unroll
        for (int mi = 0; mi < 4; ++mi)
#pragma unroll
            for (int ni = 0; ni < 4; ++ni)
                mma_f16(acc[mi][ni], af[mi], &bf[ni >> 1][(ni & 1) * 2]);
    }

    // epilogue: + b_proj[d] + q_flat[m, d]  (q fp16)
#pragma unroll
    for (int mi = 0; mi < 4; ++mi) {
#pragma unroll
        for (int ni = 0; ni < 4; ++ni) {
            int d = d0 + wn + ni * 8 + 2 * lc;
            int h = (d >> 6) & 7, e = d & 63;
            float bp0 = bproj[d], bp1 = bproj[d + 1];
#pragma unroll
            for (int half = 0; half < 2; ++half) {
                int m = m0 + wm + mi * 16 + lr + half * 8;
                int n = m & 4095;
                __half2 qh = *(const __half2*)&g_qkv[((size_t)(bb * HH + h) * NN + n)
                                                     * HD + e];
                float2 q = __half22float2(qh);
                float* op = &out[(size_t)m * CC + d];
                op[0] = acc[mi][ni][half * 2 + 0] + bp0 + q.x;
                op[1] = acc[mi][ni][half * 2 + 1] + bp1 + q.y;
            }
        }
    }
}

// ---------------------------------------------------------------------------
// Kernel 2: attention pooling (fp16 source rows, fp32 math), 512 threads.
// pass2==0: src=q, weight=w_q[h]           -> g_gq
// pass2==1: src=k, weight=w_k[h]*g_gq[b,h] -> g_gk
// ---------------------------------------------------------------------------
__global__ void __launch_bounds__(512) pool_kernel(const float* __restrict__ wh,
                                                   int pass2)
{
    __shared__ float logits[NN];
    __shared__ float ws[HD];
    __shared__ float red[16][HD];
    __shared__ float rscratch[16];

    const int bh = blockIdx.x;
    const int h  = bh & 7;
    const int tid  = threadIdx.x;
    const int lane = tid & 31;
    const int warp = tid >> 5;

    const __half* src = g_qkv + (pass2 ? (size_t)BHNHD : 0) + (size_t)bh * NN * HD;
    float* gout = pass2 ? g_gk : g_gq;

    if (tid < HD) {
        float w = wh[h * HD + tid] * SCALE;
        if (pass2) w *= g_gq[bh * HD + tid];
        ws[tid] = w;
    }
    __syncthreads();

    const float w0 = ws[2 * lane], w1 = ws[2 * lane + 1];

    float lmax = -1e30f;
    for (int n = warp; n < NN; n += 16) {
        float2 r = __half22float2(*(const __half2*)(src + (size_t)n * HD + 2 * lane));
        float v = r.x * w0 + r.y * w1;
#pragma unroll
        for (int o = 16; o; o >>= 1) v += __shfl_xor_sync(0xffffffffu, v, o);
        if (lane == 0) logits[n] = v;
        lmax = fmaxf(lmax, v);
    }
    if (lane == 0) rscratch[warp] = lmax;
    __syncthreads();
    if (tid == 0) {
        float m = rscratch[0];
        for (int i = 1; i < 16; i++) m = fmaxf(m, rscratch[i]);
        rscratch[0] = m;
    }
    __syncthreads();
    const float gmax = rscratch[0];
    __syncthreads();

    float lsum = 0.0f;
    for (int n = tid; n < NN; n += 512) {
        float e = expf(logits[n] - gmax);
        logits[n] = e;
        lsum += e;
    }
#pragma unroll
    for (int o = 16; o; o >>= 1) lsum += __shfl_xor_sync(0xffffffffu, lsum, o);
    if (lane == 0) rscratch[warp] = lsum;
    __syncthreads();
    if (tid == 0) {
        float s = 0.0f;
        for (int i = 0; i < 16; i++) s += rscratch[i];
        rscratch[0] = s;
    }
    __syncthreads();
    const float inv = 1.0f / rscratch[0];

    float a0 = 0.0f, a1 = 0.0f;
    for (int n = warp; n < NN; n += 16) {
        float p = logits[n];
        float2 r = __half22float2(*(const __half2*)(src + (size_t)n * HD + 2 * lane));
        a0 += p * r.x;
        a1 += p * r.y;
    }
    red[warp][2 * lane] = a0;
    red[warp][2 * lane + 1] = a1;
    __syncthreads();
    if (tid < HD) {
        float s = 0.0f;
#pragma unroll
        for (int w = 0; w < 16; w++) s += red[w][tid];
        gout[bh * HD + tid] = s * inv;
    }
}

// ---------------------------------------------------------------------------
extern "C" void kernel_launch(void* const* d_in, const int* in_sizes, int n_in,
                              void* d_out, int out_size)
{
    const float* x      = (const float*)d_in[0];
    const float* w_qkv  = (const float*)d_in[1];
    const float* w_proj = (const float*)d_in[2];
    const float* b_proj = (const float*)d_in[3];
    const float* w_q    = (const float*)d_in[4];
    const float* w_k    = (const float*)d_in[5];
    float* out = (float*)d_out;

    static bool s_init = [] {
        cudaFuncSetAttribute(qkv_gemm_h,
                             cudaFuncAttributeMaxDynamicSharedMemorySize, SMEM_GEMM);
        cudaFuncSetAttribute(out_gemm_h,
                             cudaFuncAttributeMaxDynamicSharedMemorySize, SMEM_GEMM);
        return true;
    }();
    (void)s_init;

    __half* xh; cudaGetSymbolAddress((void**)&xh, g_xh);
    __half* w1h; cudaGetSymbolAddress((void**)&w1h, g_w1h);
    __half* w2h; cudaGetSymbolAddress((void**)&w2h, g_w2h);

    f2h_kernel<<<2048, 256>>>(x, xh, (BB * NN * CC) / 4);
    f2h_kernel<<<256, 256>>>(w_qkv, w1h, (3 * CC * CC) / 4);
    f2h_kernel<<<256, 256>>>(w_proj, w2h, (CC * CC) / 4);

    qkv_gemm_h<<<dim3(1536 / 128, 32768 / 256), 512, SMEM_GEMM>>>(xh, w1h);
    pool_kernel<<<BB * HH, 512>>>(w_q, 0);
    pool_kernel<<<BB * HH, 512>>>(w_k, 1);
    out_gemm_h<<<dim3(512 / 128, 32768 / 256), 512, SMEM_GEMM>>>(w2h, b_proj, out);
}